// round 13
// baseline (speedup 1.0000x reference)
#include <cuda_runtime.h>

// ExpectationSoftmaxLayer: s[b,o] = sum_i p*z, p = softmax(tau*z, i),
// z[b,o,i] = x[b,i] * leaky_clamp(w[o,i], 0, 1, 0.1)
//
// R13 strategy (scalar MUFU/FMA pipe balancing; f32x2 removed — it decomposes
// on sm_103a and gave no pipe benefit, only reg pressure + ALU movs):
//   Pass 1: awk[o,i] = leaky_clamp(w[o,i]) * k,  k = exp(log_tau)*log2(e)
//   Pass 2: arg = x*awk (log2 domain). e = 2^arg via:
//             - ex2.approx.f32 (MUFU) on 5 of 8 register tiles
//             - deg-5 Taylor Horner (FMA pipe) on 3 of 8 tiles
//           num += arg*e, den += e;  s = (num/den)/k.
//   Tile = 4(b) x 2(o) per warp, lanes stride i (coalesced LDG.128),
//   butterfly reduce at the end.

#define B_    256
#define IN_   1024
#define OUT_  1024

#define RB_B  4
#define RB_O  2
#define WARPS 8

#define LOG2E 1.4426950408889634f

__device__ float g_awk[OUT_ * IN_];

__device__ __forceinline__ float ex2f(float a) {
    float r;
    asm("ex2.approx.ftz.f32 %0, %1;" : "=f"(r) : "f"(a));
    return r;
}

// 2^a, deg-5 Taylor (coeffs ln2^k/k!). |a| <= ~0.7 in practice -> rel err <= 3e-6.
__device__ __forceinline__ float exp2_poly(float a) {
    float r = fmaf(1.3333558e-3f, a, 9.6181291e-3f);
    r = fmaf(r, a, 5.5504109e-2f);
    r = fmaf(r, a, 2.4022651e-1f);
    r = fmaf(r, a, 6.9314718e-1f);
    r = fmaf(r, a, 1.0f);
    return r;
}

// leaky_clamp(x, 0, 1, 0.1) == 0.1*x + 0.9*saturate(x)
__device__ __forceinline__ float leaky_clamp01(float v) {
    return fmaf(0.9f, __saturatef(v), 0.1f * v);
}

__global__ __launch_bounds__(256)
void prep_awk_kernel(const float* __restrict__ w,
                     const float* __restrict__ log_tau) {
    const float k = expf(log_tau[0]) * LOG2E;
    int idx = (blockIdx.x * blockDim.x + threadIdx.x) * 4;
    float4 v = *reinterpret_cast<const float4*>(w + idx);
    float4 o;
    o.x = leaky_clamp01(v.x) * k;
    o.y = leaky_clamp01(v.y) * k;
    o.z = leaky_clamp01(v.z) * k;
    o.w = leaky_clamp01(v.w) * k;
    *reinterpret_cast<float4*>(g_awk + idx) = o;
}

__global__ __launch_bounds__(256, 4)
void esl_main_kernel(const float* __restrict__ x,
                     const float* __restrict__ log_tau,
                     float* __restrict__ out) {
    const int lane = threadIdx.x & 31;
    const int warp = threadIdx.x >> 5;

    const int o0 = (blockIdx.x * WARPS + warp) * RB_O;
    const int b0 = blockIdx.y * RB_B;

    const float* __restrict__ xrow = x + (size_t)b0 * IN_ + lane * 4;
    const float* __restrict__ arow = g_awk + (size_t)o0 * IN_ + lane * 4;

    float num[RB_B * RB_O];
    float den[RB_B * RB_O];
#pragma unroll
    for (int t = 0; t < RB_B * RB_O; t++) { num[t] = 0.f; den[t] = 0.f; }

#pragma unroll 1
    for (int it = 0; it < IN_ / 128; it++) {
        const int ic = it * 128;

        float4 xv[RB_B];
        float4 av[RB_O];
#pragma unroll
        for (int rb = 0; rb < RB_B; rb++)
            xv[rb] = *reinterpret_cast<const float4*>(xrow + rb * IN_ + ic);
#pragma unroll
        for (int ro = 0; ro < RB_O; ro++)
            av[ro] = *reinterpret_cast<const float4*>(arow + ro * IN_ + ic);

#pragma unroll
        for (int rb = 0; rb < RB_B; rb++) {
            const float xs[4] = {xv[rb].x, xv[rb].y, xv[rb].z, xv[rb].w};
#pragma unroll
            for (int ro = 0; ro < RB_O; ro++) {
                const float as[4] = {av[ro].x, av[ro].y, av[ro].z, av[ro].w};
                const int t = rb * RB_O + ro;
                // 3 of 8 tiles on the FMA-pipe polynomial path (f = 0.375)
                const bool poly = (t == 1) || (t == 3) || (t == 6);
#pragma unroll
                for (int s = 0; s < 4; s++) {
                    float a = xs[s] * as[s];
                    float e = poly ? exp2_poly(a) : ex2f(a);
                    den[t] += e;
                    num[t] = fmaf(a, e, num[t]);
                }
            }
        }
    }

    const float inv_k = 1.0f / (expf(log_tau[0]) * LOG2E);

#pragma unroll
    for (int rb = 0; rb < RB_B; rb++) {
#pragma unroll
        for (int ro = 0; ro < RB_O; ro++) {
            const int t = rb * RB_O + ro;
            float n = num[t];
            float d = den[t];
#pragma unroll
            for (int off = 16; off > 0; off >>= 1) {
                n += __shfl_xor_sync(0xFFFFFFFFu, n, off);
                d += __shfl_xor_sync(0xFFFFFFFFu, d, off);
            }
            if (lane == 0) {
                out[(size_t)(b0 + rb) * OUT_ + (o0 + ro)] = (n / d) * inv_k;
            }
        }
    }
}

extern "C" void kernel_launch(void* const* d_in, const int* in_sizes, int n_in,
                              void* d_out, int out_size) {
    const float* x       = (const float*)d_in[0];  // (256, 1024)
    const float* weight  = (const float*)d_in[1];  // (1024, 1024)
    const float* log_tau = (const float*)d_in[2];  // scalar
    float* out           = (float*)d_out;          // (256, 1024)

    prep_awk_kernel<<<(OUT_ * IN_) / (256 * 4), 256>>>(weight, log_tau);

    dim3 grid(OUT_ / (WARPS * RB_O), B_ / RB_B);
    esl_main_kernel<<<grid, 256>>>(x, log_tau, out);
}

// round 14
// speedup vs baseline: 1.0005x; 1.0005x over previous
#include <cuda_runtime.h>

// ExpectationSoftmaxLayer: s[b,o] = sum_i p*z, p = softmax(tau*z, i),
// z[b,o,i] = x[b,i] * leaky_clamp(w[o,i], 0, 1, 0.1)
//
// R14: issue-efficiency round.
//  - x tile staged in SMEM (shared by all 8 warps of the CTA) -> LDS, lat 29.
//  - awk streamed from L2 with 1-iteration register prefetch -> latency hidden.
//  - MUFU/FMA hybrid at f = 10/32 (balance point of MUFU pipe vs issue):
//    tiles {1,3} fully poly, tile 5 half poly (compile-time, branch-free).
//  - deg-5 Taylor for 2^a (even-symmetric error -> cancels in num/den).

#define B_    256
#define IN_   1024
#define OUT_  1024

#define RB_B  4
#define RB_O  2
#define WARPS 8
#define NITER (IN_ / 128)

#define LOG2E 1.4426950408889634f

__device__ float g_awk[OUT_ * IN_];

__device__ __forceinline__ float ex2f(float a) {
    float r;
    asm("ex2.approx.ftz.f32 %0, %1;" : "=f"(r) : "f"(a));
    return r;
}

// 2^a, deg-5 Taylor (coeffs ln2^k/k!). |a| <= ~0.8 here -> rel err <= 4e-5
// at the extreme tail, ~1e-9 typical; error is even in a -> cancels in num/den.
__device__ __forceinline__ float exp2_poly(float a) {
    float r = fmaf(1.3333558e-3f, a, 9.6181291e-3f);
    r = fmaf(r, a, 5.5504109e-2f);
    r = fmaf(r, a, 2.4022651e-1f);
    r = fmaf(r, a, 6.9314718e-1f);
    r = fmaf(r, a, 1.0f);
    return r;
}

// leaky_clamp(x, 0, 1, 0.1) == 0.1*x + 0.9*saturate(x)
__device__ __forceinline__ float leaky_clamp01(float v) {
    return fmaf(0.9f, __saturatef(v), 0.1f * v);
}

__global__ __launch_bounds__(256)
void prep_awk_kernel(const float* __restrict__ w,
                     const float* __restrict__ log_tau) {
    const float k = expf(log_tau[0]) * LOG2E;
    int idx = (blockIdx.x * blockDim.x + threadIdx.x) * 4;
    float4 v = *reinterpret_cast<const float4*>(w + idx);
    float4 o;
    o.x = leaky_clamp01(v.x) * k;
    o.y = leaky_clamp01(v.y) * k;
    o.z = leaky_clamp01(v.z) * k;
    o.w = leaky_clamp01(v.w) * k;
    *reinterpret_cast<float4*>(g_awk + idx) = o;
}

__global__ __launch_bounds__(256, 4)
void esl_main_kernel(const float* __restrict__ x,
                     const float* __restrict__ log_tau,
                     float* __restrict__ out) {
    __shared__ float xs[RB_B][IN_];   // 16 KB

    const int tid  = threadIdx.x;
    const int lane = tid & 31;
    const int warp = tid >> 5;

    const int o0 = (blockIdx.x * WARPS + warp) * RB_O;
    const int b0 = blockIdx.y * RB_B;

    // Cooperative load of the CTA's x tile (4 batch rows, shared by all warps).
    {
        const float4* __restrict__ src =
            reinterpret_cast<const float4*>(x + (size_t)b0 * IN_);
        float4* dst = reinterpret_cast<float4*>(&xs[0][0]);
#pragma unroll
        for (int t = tid; t < RB_B * IN_ / 4; t += 256)
            dst[t] = src[t];
    }
    __syncthreads();

    const float* __restrict__ arow = g_awk + (size_t)o0 * IN_ + lane * 4;

    float num[RB_B * RB_O];
    float den[RB_B * RB_O];
#pragma unroll
    for (int t = 0; t < RB_B * RB_O; t++) { num[t] = 0.f; den[t] = 0.f; }

    float4 a_cur[RB_O], a_nxt[RB_O];
#pragma unroll
    for (int ro = 0; ro < RB_O; ro++)
        a_cur[ro] = *reinterpret_cast<const float4*>(arow + ro * IN_);

    // Body: consume one 128-wide i-slab for the 4x2 tile.
#define ESL_BODY(IC)                                                          \
    do {                                                                      \
        const int ic_ = (IC) + lane * 4;                                      \
        _Pragma("unroll")                                                     \
        for (int rb = 0; rb < RB_B; rb++) {                                   \
            float4 xv = *reinterpret_cast<const float4*>(&xs[rb][ic_]);       \
            const float xsc[4] = {xv.x, xv.y, xv.z, xv.w};                    \
            _Pragma("unroll")                                                 \
            for (int ro = 0; ro < RB_O; ro++) {                               \
                const int t = rb * RB_O + ro;                                 \
                const float asc[4] = {a_cur[ro].x, a_cur[ro].y,               \
                                      a_cur[ro].z, a_cur[ro].w};              \
                _Pragma("unroll")                                             \
                for (int s = 0; s < 4; s++) {                                 \
                    /* f = 10/32: tiles 1,3 full poly; tile 5 half poly */    \
                    const bool poly = (t == 1) || (t == 3) ||                 \
                                      (t == 5 && s < 2);                      \
                    float a = xsc[s] * asc[s];                                \
                    float e = poly ? exp2_poly(a) : ex2f(a);                  \
                    den[t] += e;                                              \
                    num[t] = fmaf(a, e, num[t]);                              \
                }                                                             \
            }                                                                 \
        }                                                                     \
    } while (0)

#pragma unroll 1
    for (int it = 0; it < NITER - 1; it++) {
        const int icn = (it + 1) * 128;
        // prefetch next awk slab (L2 hit ~240cyc, hidden behind full body)
#pragma unroll
        for (int ro = 0; ro < RB_O; ro++)
            a_nxt[ro] = *reinterpret_cast<const float4*>(arow + ro * IN_ + icn);

        ESL_BODY(it * 128);

#pragma unroll
        for (int ro = 0; ro < RB_O; ro++) a_cur[ro] = a_nxt[ro];
    }
    ESL_BODY((NITER - 1) * 128);
#undef ESL_BODY

    const float inv_k = 1.0f / (expf(log_tau[0]) * LOG2E);

#pragma unroll
    for (int rb = 0; rb < RB_B; rb++) {
#pragma unroll
        for (int ro = 0; ro < RB_O; ro++) {
            const int t = rb * RB_O + ro;
            float n = num[t];
            float d = den[t];
#pragma unroll
            for (int off = 16; off > 0; off >>= 1) {
                n += __shfl_xor_sync(0xFFFFFFFFu, n, off);
                d += __shfl_xor_sync(0xFFFFFFFFu, d, off);
            }
            if (lane == 0) {
                out[(size_t)(b0 + rb) * OUT_ + (o0 + ro)] = (n / d) * inv_k;
            }
        }
    }
}

extern "C" void kernel_launch(void* const* d_in, const int* in_sizes, int n_in,
                              void* d_out, int out_size) {
    const float* x       = (const float*)d_in[0];  // (256, 1024)
    const float* weight  = (const float*)d_in[1];  // (1024, 1024)
    const float* log_tau = (const float*)d_in[2];  // scalar
    float* out           = (float*)d_out;          // (256, 1024)

    prep_awk_kernel<<<(OUT_ * IN_) / (256 * 4), 256>>>(weight, log_tau);

    dim3 grid(OUT_ / (WARPS * RB_O), B_ / RB_B);
    esl_main_kernel<<<grid, 256>>>(x, log_tau, out);
}

// round 16
// speedup vs baseline: 1.1770x; 1.1764x over previous
#include <cuda_runtime.h>
#include <cuda_fp16.h>
#include <cstdint>

// ExpectationSoftmaxLayer: s[b,o] = sum_i p*z, p = softmax(tau*z, i),
// z[b,o,i] = x[b,i] * leaky_clamp(w[o,i], 0, 1, 0.1)
//
// R16: fractional f16x2-MUFU. ex2.approx.f16x2 gives 2 exps/MUFU op but has
// table error 2^-9.9; using it on q=3/8 of elements (uniformly spread per
// output via a period-4 (tile,slab) pattern) keeps output rel_err ~<=0.86e-3
// worst-case while cutting the MUFU-pipe bound 110k -> 89.7k cyc. Everything
// except the f16 exp itself stays f32 (args, products, accumulation), so the
// fma pipe stays light and the DVFS clock high (the R13/R14 lesson).

#define B_    256
#define IN_   1024
#define OUT_  1024

#define RB_B  4
#define RB_O  2
#define WARPS 8
#define NSLAB (IN_ / 128)   // 8 slabs of 128 floats

#define LOG2E 1.4426950408889634f

__device__ float g_awk[OUT_ * IN_];

__device__ __forceinline__ float ex2f(float a) {
    float r;
    asm("ex2.approx.ftz.f32 %0, %1;" : "=f"(r) : "f"(a));
    return r;
}

__device__ __forceinline__ __half2 h2ex2(__half2 x) {
    uint32_t u = *reinterpret_cast<uint32_t*>(&x);
    uint32_t v;
    asm("ex2.approx.f16x2 %0, %1;" : "=r"(v) : "r"(u));
    return *reinterpret_cast<__half2*>(&v);
}

// leaky_clamp(x, 0, 1, 0.1) == 0.1*x + 0.9*saturate(x)
__device__ __forceinline__ float leaky_clamp01(float v) {
    return fmaf(0.9f, __saturatef(v), 0.1f * v);
}

__global__ __launch_bounds__(256)
void prep_awk_kernel(const float* __restrict__ w,
                     const float* __restrict__ log_tau) {
    const float k = expf(log_tau[0]) * LOG2E;
    int idx = (blockIdx.x * blockDim.x + threadIdx.x) * 4;
    float4 v = *reinterpret_cast<const float4*>(w + idx);
    float4 o;
    o.x = leaky_clamp01(v.x) * k;
    o.y = leaky_clamp01(v.y) * k;
    o.z = leaky_clamp01(v.z) * k;
    o.w = leaky_clamp01(v.w) * k;
    *reinterpret_cast<float4*>(g_awk + idx) = o;
}

__global__ __launch_bounds__(256, 4)
void esl_main_kernel(const float* __restrict__ x,
                     const float* __restrict__ log_tau,
                     float* __restrict__ out) {
    __shared__ float xs[RB_B][IN_];   // 16 KB

    const int tid  = threadIdx.x;
    const int lane = tid & 31;
    const int warp = tid >> 5;

    const int o0 = (blockIdx.x * WARPS + warp) * RB_O;
    const int b0 = blockIdx.y * RB_B;

    // Cooperative staging of the CTA's 4 x-rows.
    {
        const float4* __restrict__ src =
            reinterpret_cast<const float4*>(x + (size_t)b0 * IN_);
        float4* dst = reinterpret_cast<float4*>(&xs[0][0]);
#pragma unroll
        for (int t = tid; t < RB_B * IN_ / 4; t += 256)
            dst[t] = src[t];
    }
    __syncthreads();

    const float* __restrict__ arow = g_awk + (size_t)o0 * IN_ + lane * 4;

    float num[RB_B * RB_O];
    float den[RB_B * RB_O];
#pragma unroll
    for (int t = 0; t < RB_B * RB_O; t++) { num[t] = 0.f; den[t] = 0.f; }

    // Double-buffered awk slabs, indexed by compile-time phase parity.
    float4 abuf[2][RB_O];
#pragma unroll
    for (int ro = 0; ro < RB_O; ro++)
        abuf[0][ro] = *reinterpret_cast<const float4*>(arow + ro * IN_);

    // One 128-wide slab for the 4x2 tile. PH = slab index & 3 (compile-time).
    // f16x2 exp on slots s0,s1 when ((t + PH) & 3) != 3  ->  q = 3/8 uniform.
#define ESL_BODY(ITG, PH)                                                     \
    do {                                                                      \
        const int ic_ = (ITG) * 128 + lane * 4;                               \
        const int icn_ = (((ITG) + 1) & (NSLAB - 1)) * 128;                   \
        /* prefetch next slab's awk into the other buffer */                  \
        _Pragma("unroll")                                                     \
        for (int ro = 0; ro < RB_O; ro++)                                     \
            abuf[((PH) + 1) & 1][ro] =                                        \
                *reinterpret_cast<const float4*>(arow + ro * IN_ + icn_);     \
        _Pragma("unroll")                                                     \
        for (int rb = 0; rb < RB_B; rb++) {                                   \
            float4 xv = *reinterpret_cast<const float4*>(&xs[rb][ic_]);       \
            _Pragma("unroll")                                                 \
            for (int ro = 0; ro < RB_O; ro++) {                               \
                float4 av = abuf[(PH) & 1][ro];                               \
                const int t = rb * RB_O + ro;                                 \
                float a0 = xv.x * av.x;                                       \
                float a1 = xv.y * av.y;                                       \
                float a2 = xv.z * av.z;                                       \
                float a3 = xv.w * av.w;                                       \
                float e0, e1;                                                 \
                if (((t + (PH)) & 3) != 3) {                                  \
                    __half2 ah = __floats2half2_rn(a0, a1);                   \
                    float2 ef = __half22float2(h2ex2(ah));                    \
                    e0 = ef.x; e1 = ef.y;                                     \
                } else {                                                      \
                    e0 = ex2f(a0); e1 = ex2f(a1);                             \
                }                                                             \
                float e2 = ex2f(a2);                                          \
                float e3 = ex2f(a3);                                          \
                den[t] += e0; num[t] = fmaf(a0, e0, num[t]);                  \
                den[t] += e1; num[t] = fmaf(a1, e1, num[t]);                  \
                den[t] += e2; num[t] = fmaf(a2, e2, num[t]);                  \
                den[t] += e3; num[t] = fmaf(a3, e3, num[t]);                  \
            }                                                                 \
        }                                                                     \
    } while (0)

#pragma unroll 1
    for (int ito = 0; ito < NSLAB / 4; ito++) {
        const int itg = ito * 4;
        ESL_BODY(itg + 0, 0);
        ESL_BODY(itg + 1, 1);
        ESL_BODY(itg + 2, 2);
        ESL_BODY(itg + 3, 3);
    }
#undef ESL_BODY

    const float inv_k = 1.0f / (expf(log_tau[0]) * LOG2E);

#pragma unroll
    for (int rb = 0; rb < RB_B; rb++) {
#pragma unroll
        for (int ro = 0; ro < RB_O; ro++) {
            const int t = rb * RB_O + ro;
            float n = num[t];
            float d = den[t];
#pragma unroll
            for (int off = 16; off > 0; off >>= 1) {
                n += __shfl_xor_sync(0xFFFFFFFFu, n, off);
                d += __shfl_xor_sync(0xFFFFFFFFu, d, off);
            }
            if (lane == 0) {
                out[(size_t)(b0 + rb) * OUT_ + (o0 + ro)] = (n / d) * inv_k;
            }
        }
    }
}

extern "C" void kernel_launch(void* const* d_in, const int* in_sizes, int n_in,
                              void* d_out, int out_size) {
    const float* x       = (const float*)d_in[0];  // (256, 1024)
    const float* weight  = (const float*)d_in[1];  // (1024, 1024)
    const float* log_tau = (const float*)d_in[2];  // scalar
    float* out           = (float*)d_out;          // (256, 1024)

    prep_awk_kernel<<<(OUT_ * IN_) / (256 * 4), 256>>>(weight, log_tau);

    dim3 grid(OUT_ / (WARPS * RB_O), B_ / RB_B);
    esl_main_kernel<<<grid, 256>>>(x, log_tau, out);
}